// round 1
// baseline (speedup 1.0000x reference)
#include <cuda_runtime.h>
#include <math.h>

#define BATCH 16
#define CIN 512
#define COUT 512
#define HH 32
#define WDIM 512

// Scratch (no allocations allowed)
__device__ float g_style[BATCH * CIN];    // modulated style s[b][ci]
__device__ float g_dcoef[BATCH * COUT];   // demod coefficient per (b,co)
__device__ float g_wsq[COUT * CIN];       // sum_k conv_weight[co,ci,k]^2

// ---------------------------------------------------------------------------
// Kernel 0: wsq[co,ci] = sum over 3x3 taps of conv_weight^2
// ---------------------------------------------------------------------------
__global__ void wsq_kernel(const float* __restrict__ cw) {
    int idx = blockIdx.x * blockDim.x + threadIdx.x;
    if (idx < COUT * CIN) {
        const float* p = cw + (size_t)idx * 9;
        float s = 0.f;
#pragma unroll
        for (int k = 0; k < 9; k++) { float v = p[k]; s += v * v; }
        g_wsq[idx] = s;
    }
}

// ---------------------------------------------------------------------------
// Kernel 1: style[b,ci] = (w_latent[b] . affine_weight[ci]) / sqrt(512) + bias
// ---------------------------------------------------------------------------
__global__ void style_kernel(const float* __restrict__ wl,
                             const float* __restrict__ aw,
                             const float* __restrict__ ab) {
    int b = blockIdx.x;
    int ci = threadIdx.x;
    __shared__ float sw[WDIM];
    sw[ci] = wl[b * WDIM + ci];
    __syncthreads();
    const float* row = aw + (size_t)ci * WDIM;
    float acc = 0.f;
#pragma unroll 8
    for (int k = 0; k < WDIM; k++) acc += sw[k] * row[k];
    g_style[b * CIN + ci] = acc * 0.04419417382415922f + ab[ci];  // 1/sqrt(512)
}

// ---------------------------------------------------------------------------
// Kernel 2: dcoef[b,co] = rsqrt( sum_ci style[b,ci]^2 * wsq[co,ci] + 1e-8 )
// ---------------------------------------------------------------------------
__global__ void dcoef_kernel() {
    int b = blockIdx.x;
    int co = threadIdx.x;  // also spans ci (CIN == COUT == 512)
    __shared__ float s2[CIN];
    float st = g_style[b * CIN + co];
    s2[co] = st * st;
    __syncthreads();
    const float* row = g_wsq + (size_t)co * CIN;
    float acc = 0.f;
#pragma unroll 8
    for (int ci = 0; ci < CIN; ci++) acc += s2[ci] * row[ci];
    g_dcoef[b * COUT + co] = rsqrtf(acc + 1e-8f);
}

// ---------------------------------------------------------------------------
// Kernel 3: main fused conv-transpose(stride 2) + FIR + noise/bias/lrelu/clamp
//
// Intermediate y is 65x65 per (b,co):
//   y[2m+s, 2n+t] accumulated per 2x2 "cell" (m,n) in [0,33)^2:
//     y[2m,2n]     = x[m,n]w00 + x[m,n-1]w02 + x[m-1,n]w20 + x[m-1,n-1]w22
//     y[2m,2n+1]   = x[m,n]w01 + x[m-1,n]w21
//     y[2m+1,2n]   = x[m,n]w10 + x[m,n-1]w12
//     y[2m+1,2n+1] = x[m,n]w11
//   (cells with 2m+s or 2n+t > 64 are dropped)
// FIR: out[u,v] = sum_{a,b in [0,4)} f[a]f[b]/16 * ypad[u+a][v+b],
//   ypad[i][j] = y[i-1][j-1], zero borders (incl. y[65] := 0).
// ---------------------------------------------------------------------------
__global__ __launch_bounds__(256) void conv_kernel(
    const float* __restrict__ x, const float* __restrict__ cw,
    const float* __restrict__ noise, const float* __restrict__ nstr,
    const float* __restrict__ bias, float* __restrict__ out) {
    const int co = blockIdx.x, b = blockIdx.y;
    const int tid = threadIdx.x;

    __shared__ float xp[34][36];  // x padded by 1 (zeros at border), row stride 36
    __shared__ float yp[67][68];  // ypad, zero borders

    for (int i = tid; i < 34 * 36; i += 256) ((float*)xp)[i] = 0.f;
    for (int i = tid; i < 67 * 68; i += 256) ((float*)yp)[i] = 0.f;

    // Cell assignment: cell id = tid + 256*i, i in [0,5); 33*33 = 1089 cells.
    // Slots 0..3 always valid (max id 1023); slot 4 valid iff tid < 65.
    float acc[5][4];
#pragma unroll
    for (int i = 0; i < 5; i++)
#pragma unroll
        for (int j = 0; j < 4; j++) acc[i][j] = 0.f;

    int cm[5], cn[5];
#pragma unroll
    for (int i = 0; i < 5; i++) {
        int c = tid + 256 * i;
        cm[i] = c / 33;
        cn[i] = c % 33;
    }
    const bool v4 = (tid + 1024) < 1089;

    const float* xb  = x + (size_t)b * CIN * (HH * HH);
    const float* cwc = cw + (size_t)co * CIN * 9;
    const float* stb = g_style + b * CIN;

    __syncthreads();

    for (int ci = 0; ci < CIN; ci++) {
        // cooperative load of 32x32 x tile into padded smem (4 floats/thread)
        float4 xv = ((const float4*)(xb + ci * 1024))[tid];
        int e = tid * 4;
        int r = (e >> 5) + 1;
        int c0 = (e & 31) + 1;
        xp[r][c0] = xv.x; xp[r][c0 + 1] = xv.y;
        xp[r][c0 + 2] = xv.z; xp[r][c0 + 3] = xv.w;
        __syncthreads();

        float s = stb[ci];
        float w[9];
#pragma unroll
        for (int k = 0; k < 9; k++) w[k] = cwc[ci * 9 + k] * s;

#pragma unroll
        for (int i = 0; i < 5; i++) {
            if (i == 4 && !v4) break;
            const float* p = &xp[cm[i]][cn[i]];
            float a00 = p[0], a01 = p[1], a10 = p[36], a11 = p[37];
            // a11 = x[m,n], a10 = x[m,n-1], a01 = x[m-1,n], a00 = x[m-1,n-1]
            acc[i][0] += a11 * w[0];
            acc[i][0] += a10 * w[2];
            acc[i][0] += a01 * w[6];
            acc[i][0] += a00 * w[8];
            acc[i][1] += a11 * w[1];
            acc[i][1] += a01 * w[7];
            acc[i][2] += a11 * w[3];
            acc[i][2] += a10 * w[5];
            acc[i][3] += a11 * w[4];
        }
        __syncthreads();
    }

    // write cells into padded y with demod scaling
    const float dc = g_dcoef[b * COUT + co];
#pragma unroll
    for (int i = 0; i < 5; i++) {
        if (i == 4 && !v4) break;
        int m = cm[i], n = cn[i];
        yp[2 * m + 1][2 * n + 1] = acc[i][0] * dc;
        if (n < 32) yp[2 * m + 1][2 * n + 2] = acc[i][1] * dc;
        if (m < 32) yp[2 * m + 2][2 * n + 1] = acc[i][2] * dc;
        if (m < 32 && n < 32) yp[2 * m + 2][2 * n + 2] = acc[i][3] * dc;
    }
    __syncthreads();

    // FIR (separable [1,3,3,1]/4 each dim) + noise + bias + lrelu + clamp
    const float nst = nstr[0];
    const float bc = bias[co];
    const float* nzb = noise + (size_t)b * 4096;
    float* ob = out + (((size_t)b * COUT + co) << 12);
    const float fw0 = 0.25f, fw1 = 0.75f;

#pragma unroll 4
    for (int j = 0; j < 16; j++) {
        int px = tid + 256 * j;
        int u = px >> 6, v = px & 63;
        float sum = 0.f;
#pragma unroll
        for (int a = 0; a < 4; a++) {
            float fa = (a == 0 || a == 3) ? fw0 : fw1;
            float rs = fw0 * yp[u + a][v] + fw1 * yp[u + a][v + 1] +
                       fw1 * yp[u + a][v + 2] + fw0 * yp[u + a][v + 3];
            sum += fa * rs;
        }
        float val = sum + nzb[px] * nst + bc;
        val = (val > 0.f) ? val : 0.2f * val;   // leaky_relu 0.2
        val *= 1.4142135623730951f;             // gain sqrt(2)
        val = fminf(fmaxf(val, -256.f), 256.f); // clamp
        ob[px] = val;
    }
}

// ---------------------------------------------------------------------------
// Launch
// inputs: 0:x 1:w_latent 2:affine_weight 3:affine_bias 4:conv_weight
//         5:noise 6:noise_strength 7:bias
// ---------------------------------------------------------------------------
extern "C" void kernel_launch(void* const* d_in, const int* in_sizes, int n_in,
                              void* d_out, int out_size) {
    const float* x  = (const float*)d_in[0];
    const float* wl = (const float*)d_in[1];
    const float* aw = (const float*)d_in[2];
    const float* ab = (const float*)d_in[3];
    const float* cw = (const float*)d_in[4];
    const float* nz = (const float*)d_in[5];
    const float* ns = (const float*)d_in[6];
    const float* bs = (const float*)d_in[7];
    float* out = (float*)d_out;

    wsq_kernel<<<(COUT * CIN + 255) / 256, 256>>>(cw);
    style_kernel<<<BATCH, 512>>>(wl, aw, ab);
    dcoef_kernel<<<BATCH, 512>>>();

    dim3 grid(COUT, BATCH);  // co fastest -> blocks sharing x[b] co-resident in L2
    conv_kernel<<<grid, 256>>>(x, cw, nz, ns, bs, out);
}